// round 3
// baseline (speedup 1.0000x reference)
#include <cuda_runtime.h>
#include <cuda_bf16.h>
#include <mma.h>

using namespace nvcuda;

// Problem constants
#define MM     8192      // BATCH*SEQ
#define DMODEL 1024
#define DINNER 2048
#define DSTATE 16
#define NBATCH 4
#define SEQLEN 2048

// ---------------- scratch (device globals: allocation-free) ----------------
__device__ float g_u [MM * DINNER];   // silu(x_proj)
__device__ float g_sz[MM * DINNER];   // silu(z)
__device__ float g_dt[MM * DINNER];   // softplus(dt)
__device__ float g_xd[MM * 32];       // [B|C] projection
__device__ float g_ym[MM * DINNER];   // y * silu(z)

__device__ __forceinline__ float siluf(float v) {
    return v / (1.f + __expf(-v));
}
__device__ __forceinline__ float softplusf(float v) {
    return fmaxf(v, 0.f) + log1pf(__expf(-fabsf(v)));
}
__device__ __forceinline__ float ex2(float x) {
    float r;
    asm("ex2.approx.f32 %0, %1;" : "=f"(r) : "f"(x));
    return r;
}

// ---------------- cp.async helpers ----------------------------------------
__device__ __forceinline__ void cp16(void* s, const void* g) {
    unsigned sa = (unsigned)__cvta_generic_to_shared(s);
    asm volatile("cp.async.cg.shared.global [%0], [%1], 16;\n" :: "r"(sa), "l"(g));
}
__device__ __forceinline__ void cp_commit() {
    asm volatile("cp.async.commit_group;\n" ::: "memory");
}
template<int N>
__device__ __forceinline__ void cp_wait() {
    asm volatile("cp.async.wait_group %0;\n" :: "n"(N) : "memory");
}

// ---------------- tf32 WMMA GEMM (2-stage cp.async pipeline) ---------------
// C = A[MxK] @ B[KxN] + bias, epilogue:
//   EPI 0: silu + split (cols<2048 -> out0, else -> out1)
//   EPI 1: softplus -> out0
//   EPI 2: plain    -> out0
// Block tile 128x128, K-step 32. Dynamic smem, double-buffered.
constexpr int AS_STRIDE = 40;           // 32 + 8 pad
constexpr int BS_STRIDE = 136;          // 128 + 8 pad
constexpr int AS_TILE   = 128 * AS_STRIDE;   // 5120 floats
constexpr int BS_TILE   = 32 * BS_STRIDE;    // 4352 floats
constexpr int EPI_FLOATS = 8 * 256;          // 2048 floats
constexpr int GEMM_SMEM_BYTES =
    (2 * AS_TILE + 2 * BS_TILE + EPI_FLOATS) * 4;   // 83968 B

template<int EPI>
__global__ __launch_bounds__(256) void gemm_tf32(
    const float* __restrict__ A, const float* __restrict__ B,
    const float* __restrict__ bias,
    float* __restrict__ out0, float* __restrict__ out1,
    int M, int N, int K)
{
    extern __shared__ float smem[];
    float* As  = smem;                       // [2][128][40]
    float* Bs  = smem + 2 * AS_TILE;         // [2][32][136]
    float* Epi = smem + 2 * AS_TILE + 2 * BS_TILE;  // [8][16][16]

    const int tid  = threadIdx.x;
    const int wid  = tid >> 5;
    const int lane = tid & 31;
    const int wm   = wid >> 2;   // 0..1 (64 rows each)
    const int wn   = wid & 3;    // 0..3 (32 cols each)
    const int m0   = blockIdx.y * 128;
    const int n0   = blockIdx.x * 128;

    // per-thread load coordinates (fixed across k-steps)
    const int arow = tid >> 3;            // + r*32 rows
    const int acol = (tid & 7) << 2;
    const int brow = tid >> 5;            // + r*8 rows
    const int bcol = (tid & 31) << 2;

    wmma::fragment<wmma::accumulator, 16, 16, 8, float> acc[4][2];
    #pragma unroll
    for (int i = 0; i < 4; i++)
        #pragma unroll
        for (int j = 0; j < 2; j++)
            wmma::fill_fragment(acc[i][j], 0.f);

    const int NIT = K >> 5;  // K/32

    // prologue: fill buffer 0
    {
        float* da = As;
        float* db = Bs;
        #pragma unroll
        for (int r = 0; r < 4; r++) {
            int row = arow + r * 32;
            cp16(&da[row * AS_STRIDE + acol],
                 &A[(size_t)(m0 + row) * K + acol]);
        }
        #pragma unroll
        for (int r = 0; r < 4; r++) {
            int row = brow + r * 8;
            cp16(&db[row * BS_STRIDE + bcol],
                 &B[(size_t)row * N + n0 + bcol]);
        }
        cp_commit();
    }

    for (int it = 0; it < NIT; it++) {
        const int buf = it & 1;
        if (it + 1 < NIT) {
            const int k1 = (it + 1) << 5;
            float* da = As + (buf ^ 1) * AS_TILE;
            float* db = Bs + (buf ^ 1) * BS_TILE;
            #pragma unroll
            for (int r = 0; r < 4; r++) {
                int row = arow + r * 32;
                cp16(&da[row * AS_STRIDE + acol],
                     &A[(size_t)(m0 + row) * K + k1 + acol]);
            }
            #pragma unroll
            for (int r = 0; r < 4; r++) {
                int row = brow + r * 8;
                cp16(&db[row * BS_STRIDE + bcol],
                     &B[(size_t)(k1 + row) * N + n0 + bcol]);
            }
            cp_commit();
            cp_wait<1>();   // tile `it` complete (one group still in flight)
        } else {
            cp_wait<0>();
        }
        __syncthreads();

        const float* ca = As + buf * AS_TILE;
        const float* cb = Bs + buf * BS_TILE;
        #pragma unroll
        for (int kk = 0; kk < 32; kk += 8) {
            wmma::fragment<wmma::matrix_a, 16, 16, 8, wmma::precision::tf32, wmma::row_major> af[4];
            wmma::fragment<wmma::matrix_b, 16, 16, 8, wmma::precision::tf32, wmma::row_major> bf[2];
            #pragma unroll
            for (int i = 0; i < 4; i++) {
                wmma::load_matrix_sync(af[i],
                    &ca[(wm * 64 + i * 16) * AS_STRIDE + kk], AS_STRIDE);
                #pragma unroll
                for (int t = 0; t < af[i].num_elements; t++)
                    af[i].x[t] = wmma::__float_to_tf32(af[i].x[t]);
            }
            #pragma unroll
            for (int j = 0; j < 2; j++) {
                wmma::load_matrix_sync(bf[j],
                    &cb[kk * BS_STRIDE + wn * 32 + j * 16], BS_STRIDE);
                #pragma unroll
                for (int t = 0; t < bf[j].num_elements; t++)
                    bf[j].x[t] = wmma::__float_to_tf32(bf[j].x[t]);
            }
            #pragma unroll
            for (int i = 0; i < 4; i++)
                #pragma unroll
                for (int j = 0; j < 2; j++)
                    wmma::mma_sync(acc[i][j], af[i], bf[j], acc[i][j]);
        }
        __syncthreads();   // protects buf^1 before next prefetch overwrites
    }

    // Epilogue: frag-by-frag through per-warp smem
    float* EpiW = Epi + wid * 256;
    #pragma unroll
    for (int i = 0; i < 4; i++) {
        #pragma unroll
        for (int j = 0; j < 2; j++) {
            wmma::store_matrix_sync(EpiW, acc[i][j], 16, wmma::mem_row_major);
            __syncwarp();
            int gr0 = m0 + wm * 64 + i * 16;
            int gc0 = n0 + wn * 32 + j * 16;
            #pragma unroll
            for (int e = 0; e < 8; e++) {
                int idx = lane + e * 32;
                int r = idx >> 4, c = idx & 15;
                int gr = gr0 + r, gc = gc0 + c;
                float v = EpiW[r * 16 + c] + bias[gc];
                if (EPI == 0) {
                    float sv = siluf(v);
                    if (gc < DINNER) out0[(size_t)gr * DINNER + gc] = sv;
                    else             out1[(size_t)gr * DINNER + gc - DINNER] = sv;
                } else if (EPI == 1) {
                    out0[(size_t)gr * DINNER + gc] = softplusf(v);
                } else {
                    out0[(size_t)gr * (size_t)N + gc] = v;
                }
            }
            __syncwarp();
        }
    }
}

// ---------------- skinny projection: xdbl = u @ W_xproj + b --------------
__global__ __launch_bounds__(256) void xproj_kernel(
    const float* __restrict__ u, const float* __restrict__ W,
    const float* __restrict__ bias, float* __restrict__ xdbl)
{
    __shared__ float Ws[32][33];
    const int wid  = threadIdx.x >> 5;
    const int lane = threadIdx.x & 31;
    const int row  = blockIdx.x * 8 + wid;

    float acc = 0.f;
    for (int k0 = 0; k0 < DINNER; k0 += 32) {
        #pragma unroll
        for (int r = 0; r < 4; r++) {
            int idx = threadIdx.x + r * 256;
            Ws[idx >> 5][idx & 31] = W[(size_t)(k0 + (idx >> 5)) * 32 + (idx & 31)];
        }
        __syncthreads();
        float a = u[(size_t)row * DINNER + k0 + lane];
        #pragma unroll
        for (int i = 0; i < 32; i++)
            acc = fmaf(__shfl_sync(0xffffffffu, a, i), Ws[i][lane], acc);
        __syncthreads();
    }
    xdbl[(size_t)row * 32 + lane] = acc + bias[lane];
}

// ---------------- selective scan (fused * silu(z)) -----------------------
// layout: warp = 8 d-channels x 4 lanes; each lane owns 4 states
__global__ __launch_bounds__(256) void scan_kernel(
    const float* __restrict__ u, const float* __restrict__ dt,
    const float* __restrict__ xdbl, const float* __restrict__ sz,
    const float* __restrict__ A_log, const float* __restrict__ Dp,
    float* __restrict__ ym)
{
    __shared__ float XD[32][32];   // [t][B(16)|C(16)]
    __shared__ float Us[32][64];
    __shared__ float Ts[32][64];
    __shared__ float Zs[32][64];

    const int b    = blockIdx.y;
    const int d0   = blockIdx.x * 64;
    const int tid  = threadIdx.x;
    const int wid  = tid >> 5;
    const int lane = tid & 31;
    const int dq   = lane >> 2;       // 0..7
    const int sq   = lane & 3;        // 0..3 -> states [4sq, 4sq+3]
    const int dl   = wid * 8 + dq;    // local d 0..63
    const int d    = d0 + dl;

    float Ap[4], h[4] = {0.f, 0.f, 0.f, 0.f};
    #pragma unroll
    for (int i = 0; i < 4; i++)
        Ap[i] = -__expf(A_log[d * DSTATE + sq * 4 + i]) * 1.4426950408889634f;
    const float Dv = Dp[d];
    const size_t base = (size_t)b * SEQLEN * DINNER;

    for (int t0 = 0; t0 < SEQLEN; t0 += 32) {
        #pragma unroll
        for (int r = 0; r < 4; r++) {
            int idx = tid + r * 256;
            XD[idx >> 5][idx & 31] =
                xdbl[((size_t)b * SEQLEN + t0 + (idx >> 5)) * 32 + (idx & 31)];
        }
        #pragma unroll
        for (int r = 0; r < 8; r++) {
            int idx = tid + r * 256;
            int tt = idx >> 6, j = idx & 63;
            size_t g = base + (size_t)(t0 + tt) * DINNER + d0 + j;
            Us[tt][j] = u[g];
            Ts[tt][j] = dt[g];
            Zs[tt][j] = sz[g];
        }
        __syncthreads();

        #pragma unroll 4
        for (int t = 0; t < 32; t++) {
            float dtv = Ts[t][dl];
            float uv  = Us[t][dl];
            float du  = dtv * uv;
            float p   = 0.f;
            #pragma unroll
            for (int i = 0; i < 4; i++) {
                float e = ex2(dtv * Ap[i]);
                h[i] = fmaf(h[i], e, du * XD[t][sq * 4 + i]);
                p    = fmaf(h[i], XD[t][16 + sq * 4 + i], p);
            }
            p += __shfl_xor_sync(0xffffffffu, p, 1);
            p += __shfl_xor_sync(0xffffffffu, p, 2);
            if (sq == 0) {
                float y = p + Dv * uv;
                ym[base + (size_t)(t0 + t) * DINNER + d] = y * Zs[t][dl];
            }
        }
        __syncthreads();
    }
}

// ---------------- launch ---------------------------------------------------
extern "C" void kernel_launch(void* const* d_in, const int* in_sizes, int n_in,
                              void* d_out, int out_size)
{
    const float* x     = (const float*)d_in[0];
    const float* W_in  = (const float*)d_in[1];
    const float* b_in  = (const float*)d_in[2];
    const float* W_xp  = (const float*)d_in[3];
    const float* b_xp  = (const float*)d_in[4];
    const float* W_dt  = (const float*)d_in[5];
    const float* b_dt  = (const float*)d_in[6];
    const float* W_out = (const float*)d_in[7];
    const float* b_out = (const float*)d_in[8];
    const float* A_log = (const float*)d_in[9];
    const float* D_par = (const float*)d_in[10];
    float* out = (float*)d_out;

    float *u, *sz, *dtb, *xd, *ym;
    cudaGetSymbolAddress((void**)&u,   g_u);
    cudaGetSymbolAddress((void**)&sz,  g_sz);
    cudaGetSymbolAddress((void**)&dtb, g_dt);
    cudaGetSymbolAddress((void**)&xd,  g_xd);
    cudaGetSymbolAddress((void**)&ym,  g_ym);

    cudaFuncSetAttribute(gemm_tf32<0>,
        cudaFuncAttributeMaxDynamicSharedMemorySize, GEMM_SMEM_BYTES);
    cudaFuncSetAttribute(gemm_tf32<1>,
        cudaFuncAttributeMaxDynamicSharedMemorySize, GEMM_SMEM_BYTES);
    cudaFuncSetAttribute(gemm_tf32<2>,
        cudaFuncAttributeMaxDynamicSharedMemorySize, GEMM_SMEM_BYTES);

    dim3 blk(256);

    // 1) xz = x @ W_in + b_in; split; silu both halves
    gemm_tf32<0><<<dim3(4096 / 128, MM / 128), blk, GEMM_SMEM_BYTES>>>(
        x, W_in, b_in, u, sz, MM, 4096, DMODEL);

    // 2) xdbl = u @ W_xproj + b_xproj
    xproj_kernel<<<MM / 8, 256>>>(u, W_xp, b_xp, xd);

    // 3) dt = softplus(u @ W_dt + b_dt)
    gemm_tf32<1><<<dim3(DINNER / 128, MM / 128), blk, GEMM_SMEM_BYTES>>>(
        u, W_dt, b_dt, dtb, nullptr, MM, DINNER, DINNER);

    // 4) selective scan + fuse * silu(z)
    scan_kernel<<<dim3(DINNER / 64, NBATCH), 256>>>(
        u, dtb, xd, sz, A_log, D_par, ym);

    // 5) out = ym @ W_out + b_out
    gemm_tf32<2><<<dim3(DMODEL / 128, MM / 128), blk, GEMM_SMEM_BYTES>>>(
        ym, W_out, b_out, out, nullptr, MM, DMODEL, DINNER);
}